// round 16
// baseline (speedup 1.0000x reference)
#include <cuda_runtime.h>
#include <cuda_bf16.h>
#include <cstdint>

#define BN 4096
#define DN 128
#define MN 8192
#define KS 4
#define QN (2*BN*DN)
#define HALFQ (BN*DN)
#define OFF_LOSS 1048576
#define OFF_IDS  1048577
#define OFF_PERP 1081345
#define DELTA 2e-2f

typedef unsigned long long ull;

// ---------- device scratch ----------
__device__ float g_Enorm[KS*MN];
__device__ float g_xnorm0[2*BN];
__device__ float g_xnormR[2*BN];
__device__ float g_res[QN];
__device__ float g_q[QN];
__device__ ull   g_min[2*BN];
__device__ unsigned g_tilemin[2*BN*64];
__device__ int   g_counts[KS*2*MN];
__device__ int   g_idx[2*BN*KS];
__device__ float g_ph[2ull*BN*MN];
__device__ __align__(16) __nv_bfloat16 g_phh[2ull*BN*MN];
__device__ __align__(16) __nv_bfloat16 g_lgh[2ull*BN*MN];
__device__ float g_Sc[(size_t)BN*BN];
__device__ unsigned g_minkey;
__device__ float g_rowlog[BN];
__device__ float g_mse[256*4];

// ---------- helpers ----------
__device__ __forceinline__ unsigned sortkey(float v) {
    unsigned u = __float_as_uint(v);
    return (u & 0x80000000u) ? ~u : (u | 0x80000000u);
}
__device__ __forceinline__ float unsortkey(unsigned k) {
    return (k & 0x80000000u) ? __uint_as_float(k & 0x7FFFFFFFu)
                             : __uint_as_float(~k);
}
__device__ __forceinline__ ull packdi(float v, int idx) {
    return ((ull)sortkey(v) << 32) | (unsigned)idx;
}
__device__ __forceinline__ uint32_t smem_u32(const void* p) {
    uint32_t a;
    asm("{ .reg .u64 t; cvta.to.shared.u64 t, %1; cvt.u32.u64 %0, t; }"
        : "=r"(a) : "l"(p));
    return a;
}
__device__ __forceinline__ void mma_t(float* c, uint32_t a0, uint32_t a1,
                                      uint32_t a2, uint32_t a3,
                                      uint32_t b0, uint32_t b1) {
    asm volatile("mma.sync.aligned.m16n8k8.row.col.f32.tf32.tf32.f32 "
        "{%0,%1,%2,%3},{%4,%5,%6,%7},{%8,%9},{%0,%1,%2,%3};"
        : "+f"(c[0]), "+f"(c[1]), "+f"(c[2]), "+f"(c[3])
        : "r"(a0), "r"(a1), "r"(a2), "r"(a3), "r"(b0), "r"(b1));
}
__device__ __forceinline__ void ldsm4(uint32_t& r0, uint32_t& r1,
                                      uint32_t& r2, uint32_t& r3, uint32_t a) {
    asm volatile("ldmatrix.sync.aligned.m8n8.x4.shared.b16 {%0,%1,%2,%3}, [%4];"
        : "=r"(r0), "=r"(r1), "=r"(r2), "=r"(r3) : "r"(a));
}
__device__ __forceinline__ void mma_bf16(float* c, uint32_t a0, uint32_t a1,
                                         uint32_t a2, uint32_t a3,
                                         uint32_t b0, uint32_t b1) {
    asm volatile("mma.sync.aligned.m16n8k16.row.col.f32.bf16.bf16.f32 "
        "{%0,%1,%2,%3},{%4,%5,%6,%7},{%8,%9},{%0,%1,%2,%3};"
        : "+f"(c[0]), "+f"(c[1]), "+f"(c[2]), "+f"(c[3])
        : "r"(a0), "r"(a1), "r"(a2), "r"(a3), "r"(b0), "r"(b1));
}
#define CP_ASYNC16(s, g) asm volatile("cp.async.ca.shared.global [%0], [%1], 16;" :: "r"(s), "l"(g))
#define CP_COMMIT()      asm volatile("cp.async.commit_group;" ::: "memory")
#define CP_WAIT1()       asm volatile("cp.async.wait_group 1;" ::: "memory")
#define CP_WAIT0()       asm volatile("cp.async.wait_group 0;" ::: "memory")

// ---------- row norms: mode 0 -> g_Enorm ; mode 3 -> g_xnorm0 AND g_xnormR ----------
__global__ __launch_bounds__(256) void k_rownorm(const float* __restrict__ Xin,
                                                 int nrows, int mode, int off) {
    int w = (blockIdx.x * 256 + threadIdx.x) >> 5;
    int lane = threadIdx.x & 31;
    if (w >= nrows) return;
    float4 v = reinterpret_cast<const float4*>(Xin + (size_t)w * DN)[lane];
    float s = v.x*v.x + v.y*v.y + v.z*v.z + v.w*v.w;
    #pragma unroll
    for (int o = 16; o; o >>= 1) s += __shfl_xor_sync(0xFFFFFFFFu, s, o);
    if (lane == 0) {
        if (mode == 0) g_Enorm[off + w] = s;
        else { g_xnorm0[off + w] = s; g_xnormR[off + w] = s; }
    }
}

// ---------- init ----------
__global__ __launch_bounds__(256) void k_init(const float* __restrict__ pcf,
                                              const float* __restrict__ plm) {
    int stride = gridDim.x * 256;
    for (int i = blockIdx.x * 256 + threadIdx.x; i < QN; i += stride) {
        g_res[i] = (i < HALFQ) ? pcf[i] : plm[i - HALFQ];
        g_q[i] = 0.0f;
    }
    for (int i = blockIdx.x * 256 + threadIdx.x; i < KS*2*MN; i += stride)
        g_counts[i] = 0;
    if (blockIdx.x == 0 && threadIdx.x == 0) g_minkey = 0xFFFFFFFFu;
}

// ---------- cmcm scores via tf32 tensor cores (raw-bit truncation; bf16 downstream) ----------
__global__ __launch_bounds__(256) void k_scorestc(const float* __restrict__ emb) {
    __shared__ __align__(16) float sA[128*36];
    __shared__ __align__(16) float sB[128*36];
    const int tid = threadIdx.x;
    const int lane = tid & 31, wid = tid >> 5;
    const int wy = wid & 3, wx = wid >> 2;
    const int stream = blockIdx.z;
    const int b0 = blockIdx.y * 128;
    const int m0 = blockIdx.x * 128;
    const float* resp = g_res + (size_t)stream * HALFQ;   // original inputs (pre-update)
    const float* Ep = emb + (size_t)(KS-1) * MN * DN;
    const float* En = g_Enorm + (KS-1)*MN;
    const float* xnorm = g_xnorm0 + stream * BN;

    float acc[2][8][4];
    #pragma unroll
    for (int mt = 0; mt < 2; mt++)
        #pragma unroll
        for (int n8 = 0; n8 < 8; n8++)
            #pragma unroll
            for (int c = 0; c < 4; c++) acc[mt][n8][c] = 0.0f;

    const uint32_t sAu = smem_u32(sA), sBu = smem_u32(sB);
    const int l4 = lane >> 2, l3 = lane & 3;

    for (int chk = 0; chk < 4; chk++) {
        int kb = chk * 32;
        #pragma unroll
        for (int i = 0; i < 4; i++) {
            int v = tid + i*256;
            int row = v >> 3, c4 = (v & 7) * 4;
            CP_ASYNC16(sAu + (uint32_t)(row*36 + c4)*4,
                       resp + (size_t)(b0 + row)*DN + kb + c4);
        }
        #pragma unroll
        for (int i = 0; i < 4; i++) {
            int v = tid + i*256;
            int row = v >> 3, c4 = (v & 7) * 4;
            CP_ASYNC16(sBu + (uint32_t)(row*36 + c4)*4,
                       Ep + (size_t)(m0 + row)*DN + kb + c4);
        }
        CP_COMMIT(); CP_WAIT0();
        __syncthreads();
        #pragma unroll
        for (int k8 = 0; k8 < 4; k8++) {
            const int kk = k8*8 + l3;
            uint32_t aH[2][4];
            #pragma unroll
            for (int mt = 0; mt < 2; mt++) {
                int r = wy*32 + mt*16 + l4;
                aH[mt][0] = __float_as_uint(sA[r*36 + kk]);
                aH[mt][1] = __float_as_uint(sA[(r+8)*36 + kk]);
                aH[mt][2] = __float_as_uint(sA[r*36 + kk + 4]);
                aH[mt][3] = __float_as_uint(sA[(r+8)*36 + kk + 4]);
            }
            #pragma unroll
            for (int n8 = 0; n8 < 8; n8++) {
                int n = wx*64 + n8*8 + l4;
                uint32_t bH0 = __float_as_uint(sB[n*36 + kk]);
                uint32_t bH1 = __float_as_uint(sB[n*36 + kk + 4]);
                #pragma unroll
                for (int mt = 0; mt < 2; mt++)
                    mma_t(acc[mt][n8], aH[mt][0], aH[mt][1], aH[mt][2], aH[mt][3], bH0, bH1);
            }
        }
        __syncthreads();
    }

    float xv[2][2];
    #pragma unroll
    for (int mt = 0; mt < 2; mt++) {
        xv[mt][0] = xnorm[b0 + wy*32 + mt*16 + l4];
        xv[mt][1] = xnorm[b0 + wy*32 + mt*16 + l4 + 8];
    }
    size_t sbase = (size_t)stream*BN*MN;
    #pragma unroll
    for (int mt = 0; mt < 2; mt++) {
        int r = b0 + wy*32 + mt*16 + l4;
        #pragma unroll
        for (int n8 = 0; n8 < 8; n8++) {
            int c0 = m0 + wx*64 + n8*8 + l3*2;
            float e0 = En[c0], e1 = En[c0+1];
            float* a = acc[mt][n8];
            float2 o0, o1;
            o0.x = -sqrtf(fmaxf((e0 + xv[mt][0]) - 2.0f*a[0], 0.0f));
            o0.y = -sqrtf(fmaxf((e1 + xv[mt][0]) - 2.0f*a[1], 0.0f));
            o1.x = -sqrtf(fmaxf((e0 + xv[mt][1]) - 2.0f*a[2], 0.0f));
            o1.y = -sqrtf(fmaxf((e1 + xv[mt][1]) - 2.0f*a[3], 0.0f));
            *(float2*)&g_ph[sbase + (size_t)r*MN + c0]     = o0;
            *(float2*)&g_ph[sbase + (size_t)(r+8)*MN + c0] = o1;
        }
    }
}

// ---------- argmin filter: tf32 GEMM (raw-bit), per-(row,tile) approx min ----------
__global__ __launch_bounds__(256) void k_argmin_tc(const float* __restrict__ emb,
                                                   int stage) {
    __shared__ __align__(16) float sA[128*36];
    __shared__ __align__(16) float sB[128*36];
    const int tid = threadIdx.x;
    const int lane = tid & 31, wid = tid >> 5;
    const int wy = wid & 3, wx = wid >> 2;
    const int stream = blockIdx.z;
    const int b0 = blockIdx.y * 128;
    const int m0 = blockIdx.x * 128;
    const float* resp = g_res + (size_t)stream * HALFQ;
    const float* Ep = emb + (size_t)stage * MN * DN;
    const float* En = g_Enorm + stage * MN;
    const float* xnorm = g_xnormR + stream * BN;

    float acc[2][8][4];
    #pragma unroll
    for (int mt = 0; mt < 2; mt++)
        #pragma unroll
        for (int n8 = 0; n8 < 8; n8++)
            #pragma unroll
            for (int c = 0; c < 4; c++) acc[mt][n8][c] = 0.0f;

    const uint32_t sAu = smem_u32(sA), sBu = smem_u32(sB);
    const int l4 = lane >> 2, l3 = lane & 3;

    for (int chk = 0; chk < 4; chk++) {
        int kb = chk * 32;
        #pragma unroll
        for (int i = 0; i < 4; i++) {
            int v = tid + i*256;
            int row = v >> 3, c4 = (v & 7) * 4;
            CP_ASYNC16(sAu + (uint32_t)(row*36 + c4)*4,
                       resp + (size_t)(b0 + row)*DN + kb + c4);
        }
        #pragma unroll
        for (int i = 0; i < 4; i++) {
            int v = tid + i*256;
            int row = v >> 3, c4 = (v & 7) * 4;
            CP_ASYNC16(sBu + (uint32_t)(row*36 + c4)*4,
                       Ep + (size_t)(m0 + row)*DN + kb + c4);
        }
        CP_COMMIT(); CP_WAIT0();
        __syncthreads();
        #pragma unroll
        for (int k8 = 0; k8 < 4; k8++) {
            const int kk = k8*8 + l3;
            uint32_t aH[2][4];
            #pragma unroll
            for (int mt = 0; mt < 2; mt++) {
                int r = wy*32 + mt*16 + l4;
                aH[mt][0] = __float_as_uint(sA[r*36 + kk]);
                aH[mt][1] = __float_as_uint(sA[(r+8)*36 + kk]);
                aH[mt][2] = __float_as_uint(sA[r*36 + kk + 4]);
                aH[mt][3] = __float_as_uint(sA[(r+8)*36 + kk + 4]);
            }
            #pragma unroll
            for (int n8 = 0; n8 < 8; n8++) {
                int n = wx*64 + n8*8 + l4;
                uint32_t bH0 = __float_as_uint(sB[n*36 + kk]);
                uint32_t bH1 = __float_as_uint(sB[n*36 + kk + 4]);
                #pragma unroll
                for (int mt = 0; mt < 2; mt++)
                    mma_t(acc[mt][n8], aH[mt][0], aH[mt][1], aH[mt][2], aH[mt][3], bH0, bH1);
            }
        }
        __syncthreads();
    }

    float xv[2][2];
    #pragma unroll
    for (int mt = 0; mt < 2; mt++) {
        xv[mt][0] = xnorm[b0 + wy*32 + mt*16 + l4];
        xv[mt][1] = xnorm[b0 + wy*32 + mt*16 + l4 + 8];
    }
    unsigned best[2][2] = {{~0u, ~0u}, {~0u, ~0u}};
    #pragma unroll
    for (int mt = 0; mt < 2; mt++)
        #pragma unroll
        for (int n8 = 0; n8 < 8; n8++) {
            int c0 = m0 + wx*64 + n8*8 + l3*2;
            float e0 = En[c0], e1 = En[c0+1];
            float* a = acc[mt][n8];
            unsigned k00 = sortkey((e0 + xv[mt][0]) - 2.0f*a[0]);
            unsigned k01 = sortkey((e1 + xv[mt][0]) - 2.0f*a[1]);
            unsigned k10 = sortkey((e0 + xv[mt][1]) - 2.0f*a[2]);
            unsigned k11 = sortkey((e1 + xv[mt][1]) - 2.0f*a[3]);
            unsigned m0v = min(k00, k01), m1v = min(k10, k11);
            if (m0v < best[mt][0]) best[mt][0] = m0v;
            if (m1v < best[mt][1]) best[mt][1] = m1v;
        }
    __syncthreads();
    unsigned* sred = (unsigned*)sA;
    #pragma unroll
    for (int mt = 0; mt < 2; mt++)
        #pragma unroll
        for (int h = 0; h < 2; h++)
            sred[(wy*32 + mt*16 + h*8 + l4)*8 + wx*4 + l3] = best[mt][h];
    __syncthreads();
    if (tid < 128) {
        unsigned kk = sred[tid*8];
        #pragma unroll
        for (int t = 1; t < 8; t++) { unsigned c = sred[tid*8 + t]; if (c < kk) kk = c; }
        g_tilemin[((size_t)stream*BN + b0 + tid)*64 + blockIdx.x] = kk;
    }
}

// ---------- argmin verify: exact serial rescore of qualifying tiles ----------
__global__ __launch_bounds__(256) void k_verify(const float* __restrict__ emb, int stage) {
    __shared__ __align__(16) float resS[DN];
    __shared__ unsigned tm[64];
    __shared__ float thrS;
    __shared__ ull red[128];
    const int row = blockIdx.x, stream = blockIdx.y, tid = threadIdx.x;
    const float* resp = g_res + (size_t)stream*HALFQ + (size_t)row*DN;
    if (tid < 32) reinterpret_cast<float4*>(resS)[tid] = reinterpret_cast<const float4*>(resp)[tid];
    if (tid < 64) tm[tid] = g_tilemin[((size_t)stream*BN + row)*64 + tid];
    __syncthreads();
    if (tid == 0) {
        unsigned mn = tm[0];
        #pragma unroll
        for (int t = 1; t < 64; t++) mn = min(mn, tm[t]);
        thrS = unsortkey(mn) + DELTA;
    }
    __syncthreads();
    const float thr = thrS;
    const float xn = g_xnormR[stream*BN + row];
    const float* Ep = emb + (size_t)stage*MN*DN;
    const float* En = g_Enorm + stage*MN;
    if (tid < 128) {
        ull best = ~0ull;
        for (int t = 0; t < 64; t++) {
            if (unsortkey(tm[t]) <= thr) {
                int m = t*128 + tid;
                const float4* Er = reinterpret_cast<const float4*>(Ep + (size_t)m*DN);
                float acc = 0.0f;
                #pragma unroll
                for (int d4 = 0; d4 < 32; d4++) {
                    float4 e4 = Er[d4];
                    float4 r4 = reinterpret_cast<float4*>(resS)[d4];
                    acc = fmaf(r4.x, e4.x, acc);
                    acc = fmaf(r4.y, e4.y, acc);
                    acc = fmaf(r4.z, e4.z, acc);
                    acc = fmaf(r4.w, e4.w, acc);
                }
                float val = (En[m] + xn) - 2.0f*acc;
                ull p = packdi(val, m);
                if (p < best) best = p;
            }
        }
        red[tid] = best;
    }
    __syncthreads();
    for (int o = 64; o > 0; o >>= 1) {
        if (tid < o) { ull c = red[tid + o]; if (c < red[tid]) red[tid] = c; }
        __syncthreads();
    }
    if (tid == 0) g_min[stream*BN + row] = red[0];
}

// ---------- gather + residual/q update + histogram + norm ----------
__global__ __launch_bounds__(256) void k_update(const float* __restrict__ emb, int stage) {
    int w = (blockIdx.x * 256 + threadIdx.x) >> 5;
    int lane = threadIdx.x & 31;
    if (w >= 2*BN) return;
    int stream = w >> 12; int b = w & (BN - 1);
    int idx = (int)(g_min[w] & 0xFFFFFFFFull);
    float4 e = reinterpret_cast<const float4*>(emb + ((size_t)stage*MN + idx)*DN)[lane];
    float4* qp = reinterpret_cast<float4*>(g_q + (size_t)w*DN);
    float4* rp = reinterpret_cast<float4*>(g_res + (size_t)w*DN);
    float4 q = qp[lane]; q.x += e.x; q.y += e.y; q.z += e.z; q.w += e.w; qp[lane] = q;
    float4 r = rp[lane]; r.x -= e.x; r.y -= e.y; r.z -= e.z; r.w -= e.w; rp[lane] = r;
    float s = r.x*r.x + r.y*r.y + r.z*r.z + r.w*r.w;
    #pragma unroll
    for (int o = 16; o; o >>= 1) s += __shfl_xor_sync(0xFFFFFFFFu, s, o);
    if (lane == 0) {
        g_xnormR[w] = s;
        g_idx[stream*BN*KS + b*KS + stage] = idx;
        atomicAdd(&g_counts[(stage*2 + stream)*MN + idx], 1);
    }
}

// ---------- row softmax + log -> bf16 outputs ----------
__global__ __launch_bounds__(256) void k_softmax() {
    __shared__ __align__(16) float srow[MN];
    __shared__ float red[256];
    int b = blockIdx.x, s = blockIdx.y, tid = threadIdx.x;
    size_t base = (size_t)s*BN*MN + (size_t)b*MN;
    const float4* src = reinterpret_cast<const float4*>(g_ph + base);
    float mx = -3.4e38f;
    #pragma unroll
    for (int k = 0; k < 8; k++) {
        float4 v = src[tid + 256*k];
        reinterpret_cast<float4*>(srow)[tid + 256*k] = v;
        mx = fmaxf(mx, fmaxf(fmaxf(v.x, v.y), fmaxf(v.z, v.w)));
    }
    red[tid] = mx; __syncthreads();
    for (int o = 128; o > 0; o >>= 1) {
        if (tid < o) red[tid] = fmaxf(red[tid], red[tid + o]);
        __syncthreads();
    }
    mx = red[0]; __syncthreads();
    float sum = 0.0f;
    #pragma unroll
    for (int k = 0; k < 8; k++) {
        float4 v = reinterpret_cast<float4*>(srow)[tid + 256*k];
        v.x = expf(v.x - mx); v.y = expf(v.y - mx);
        v.z = expf(v.z - mx); v.w = expf(v.w - mx);
        reinterpret_cast<float4*>(srow)[tid + 256*k] = v;
        sum += v.x + v.y + v.z + v.w;
    }
    red[tid] = sum; __syncthreads();
    for (int o = 128; o > 0; o >>= 1) {
        if (tid < o) red[tid] = red[tid] + red[tid + o];
        __syncthreads();
    }
    sum = red[0];
    __nv_bfloat162* dph = reinterpret_cast<__nv_bfloat162*>(g_phh + base);
    __nv_bfloat162* dlg = reinterpret_cast<__nv_bfloat162*>(g_lgh + base);
    #pragma unroll
    for (int k = 0; k < 8; k++) {
        float4 v = reinterpret_cast<float4*>(srow)[tid + 256*k];
        v.x /= sum; v.y /= sum; v.z /= sum; v.w /= sum;
        int p = (tid + 256*k) * 2;
        dph[p]   = __floats2bfloat162_rn(v.x, v.y);
        dph[p+1] = __floats2bfloat162_rn(v.z, v.w);
        dlg[p]   = __floats2bfloat162_rn(logf(v.x + 1e-10f), logf(v.y + 1e-10f));
        dlg[p+1] = __floats2bfloat162_rn(logf(v.z + 1e-10f), logf(v.w + 1e-10f));
    }
}

// ---------- Scode via bf16 mma.m16n8k16, ldmatrix, cp.async double buffer ----------
#define SCT 10240
#define SCBUF (4*SCT)
__global__ __launch_bounds__(256) void k_scode_bf16() {
    extern __shared__ __align__(16) char smc[];
    const uint32_t sb = smem_u32(smc);
    const int tid = threadIdx.x;
    const int lane = tid & 31, wid = tid >> 5;
    const int wy = wid & 3, wx = wid >> 2;
    const int i0 = (blockIdx.x & 31) * 128;
    const int j0 = (blockIdx.x >> 5) * 128;
    const __nv_bfloat16* A1g = g_phh + (size_t)i0 * MN;
    const __nv_bfloat16* A2g = g_phh + (size_t)BN*MN + (size_t)i0 * MN;
    const __nv_bfloat16* B1g = g_lgh + (size_t)BN*MN + (size_t)j0 * MN;
    const __nv_bfloat16* B2g = g_lgh + (size_t)j0 * MN;

    float acc[2][8][4];
    #pragma unroll
    for (int mi = 0; mi < 2; mi++)
        #pragma unroll
        for (int n8 = 0; n8 < 8; n8++)
            #pragma unroll
            for (int c = 0; c < 4; c++) acc[mi][n8][c] = 0.0f;

    const int m = lane >> 3, l7 = lane & 7;
    const uint32_t aoff = (uint32_t)(((m & 1)*8 + l7) * 80 + (m >> 1) * 16);
    const uint32_t boff = (uint32_t)(((m >> 1)*8 + l7) * 80 + (m & 1) * 16);

    auto stage = [&](int kc, int bsel) {
        int kb = kc * 32;
        uint32_t d0 = sb + bsel * SCBUF;
        #pragma unroll
        for (int it = 0; it < 8; it++) {
            int t = tid + it*256;
            int mat = t >> 9, r = (t >> 2) & 127, c = t & 3;
            const __nv_bfloat16* srcp = (mat == 0) ? A1g : (mat == 1) ? A2g
                                      : (mat == 2) ? B1g : B2g;
            const void* g = srcp + (size_t)r*MN + kb + c*8;
            uint32_t sdst = d0 + mat*SCT + r*80 + c*16;
            CP_ASYNC16(sdst, g);
        }
        CP_COMMIT();
    };

    stage(0, 0);
    for (int kc = 0; kc < 256; kc++) {
        if (kc + 1 < 256) { stage(kc + 1, (kc + 1) & 1); CP_WAIT1(); }
        else CP_WAIT0();
        __syncthreads();
        uint32_t base = sb + (kc & 1) * SCBUF;
        #pragma unroll
        for (int s = 0; s < 2; s++) {
            #pragma unroll
            for (int g = 0; g < 2; g++) {
                uint32_t ab = base + g*SCT + (wy*32)*80 + s*32 + aoff;
                uint32_t a0[2], a1[2], a2[2], a3[2];
                #pragma unroll
                for (int mi = 0; mi < 2; mi++)
                    ldsm4(a0[mi], a1[mi], a2[mi], a3[mi], ab + mi*16*80);
                uint32_t bbase = base + (2 + g)*SCT + (wx*64)*80 + s*32 + boff;
                #pragma unroll
                for (int gg = 0; gg < 4; gg++) {
                    uint32_t b0, b1, b2, b3;
                    ldsm4(b0, b1, b2, b3, bbase + gg*16*80);
                    #pragma unroll
                    for (int mi = 0; mi < 2; mi++) {
                        mma_bf16(acc[mi][gg*2+0], a0[mi], a1[mi], a2[mi], a3[mi], b0, b1);
                        mma_bf16(acc[mi][gg*2+1], a0[mi], a1[mi], a2[mi], a3[mi], b2, b3);
                    }
                }
            }
        }
        __syncthreads();
    }
    float lmin = 3.4e38f;
    #pragma unroll
    for (int mi = 0; mi < 2; mi++) {
        int row = i0 + wy*32 + mi*16 + (lane >> 2);
        #pragma unroll
        for (int n8 = 0; n8 < 8; n8++) {
            int col = j0 + wx*64 + n8*8 + (lane & 3)*2;
            float* c = acc[mi][n8];
            *(float2*)&g_Sc[(size_t)row*BN + col]     = make_float2(c[0], c[1]);
            *(float2*)&g_Sc[(size_t)(row+8)*BN + col] = make_float2(c[2], c[3]);
            lmin = fminf(lmin, fminf(fminf(c[0], c[1]), fminf(c[2], c[3])));
        }
    }
    float* red = (float*)smc;
    red[tid] = lmin; __syncthreads();
    for (int o = 128; o > 0; o >>= 1) {
        if (tid < o) red[tid] = fminf(red[tid], red[tid + o]);
        __syncthreads();
    }
    if (tid == 0) atomicMin(&g_minkey, sortkey(red[0]));
}

// ---------- per-row: log(diag(E)/(rowsum(E)+eps)) ----------
__global__ __launch_bounds__(256) void k_rowratio() {
    __shared__ float red[256];
    int i = blockIdx.x, tid = threadIdx.x;
    float Mx = -unsortkey(g_minkey);
    const float* row = g_Sc + (size_t)i * BN;
    float sum = 0.0f;
    #pragma unroll
    for (int k = 0; k < 16; k++) sum += expf(row[tid + 256*k] + Mx);
    red[tid] = sum; __syncthreads();
    for (int o = 128; o > 0; o >>= 1) {
        if (tid < o) red[tid] = red[tid] + red[tid + o];
        __syncthreads();
    }
    if (tid == 0) {
        float ratio = expf(row[i] + Mx) / (red[0] + 1e-5f);
        g_rowlog[i] = logf(ratio);
    }
}

// ---------- quantized = fl(x + fl(q - x)) ----------
__global__ __launch_bounds__(256) void k_quant(const float* __restrict__ pcf,
                                               const float* __restrict__ plm,
                                               float* __restrict__ out) {
    int e = blockIdx.x * 256 + threadIdx.x;
    if (e >= QN) return;
    float x = (e < HALFQ) ? pcf[e] : plm[e - HALFQ];
    float t = g_q[e] - x;
    out[e] = x + t;
}

__global__ __launch_bounds__(256) void k_ids(float* __restrict__ out) {
    int e = blockIdx.x * 256 + threadIdx.x;
    if (e < 2*BN*KS) out[OFF_IDS + e] = (float)g_idx[e];
}

__global__ __launch_bounds__(256) void k_mse(const float* __restrict__ pcf,
                                             const float* __restrict__ plm,
                                             const float* __restrict__ out) {
    __shared__ float red[256];
    int tid = threadIdx.x, bid = blockIdx.x;
    float s[4] = {0.f, 0.f, 0.f, 0.f};
    #pragma unroll
    for (int k = 0; k < 8; k++) {
        int e = bid*2048 + k*256 + tid;
        float qp = out[e], qm = out[HALFQ + e];
        float xp = pcf[e], xm = plm[e];
        float d;
        d = xp - qp; s[0] += d*d;
        d = xp - qm; s[1] += d*d;
        d = xm - qm; s[2] += d*d;
        d = xm - qp; s[3] += d*d;
    }
    #pragma unroll
    for (int c = 0; c < 4; c++) {
        red[tid] = s[c]; __syncthreads();
        for (int o = 128; o > 0; o >>= 1) {
            if (tid < o) red[tid] = red[tid] + red[tid + o];
            __syncthreads();
        }
        if (tid == 0) g_mse[bid*4 + c] = red[0];
        __syncthreads();
    }
}

__global__ __launch_bounds__(256) void k_perp(float* __restrict__ out) {
    __shared__ float red[256];
    int b = blockIdx.x, tid = threadIdx.x;
    int k = b >> 1, s = b & 1;
    const int* cnt = g_counts + (k*2 + s)*MN;
    float sum = 0.0f;
    #pragma unroll
    for (int t = 0; t < 32; t++) {
        float avg = (float)cnt[tid + 256*t] / (float)BN;
        sum += avg * logf(avg + 1e-10f);
    }
    red[tid] = sum; __syncthreads();
    for (int o = 128; o > 0; o >>= 1) {
        if (tid < o) red[tid] = red[tid] + red[tid + o];
        __syncthreads();
    }
    if (tid == 0) out[OFF_PERP + k*2 + s] = expf(-red[0]);
}

__global__ __launch_bounds__(256) void k_final(float* __restrict__ out) {
    __shared__ float red[256];
    int tid = threadIdx.x;
    float s = 0.0f;
    #pragma unroll
    for (int k = 0; k < 16; k++) s += g_rowlog[tid + 256*k];
    red[tid] = s; __syncthreads();
    for (int o = 128; o > 0; o >>= 1) {
        if (tid < o) red[tid] = red[tid] + red[tid + o];
        __syncthreads();
    }
    float Lc = -(red[0] / (float)BN);
    __syncthreads();
    float m[4];
    for (int c = 0; c < 4; c++) {
        red[tid] = g_mse[tid*4 + c]; __syncthreads();
        for (int o = 128; o > 0; o >>= 1) {
            if (tid < o) red[tid] = red[tid] + red[tid + o];
            __syncthreads();
        }
        m[c] = red[0] / (float)HALFQ;
        __syncthreads();
    }
    if (tid == 0) {
        float pcf_loss = 0.5f*m[0] + 0.25f*m[1];
        float plm_loss = 0.5f*m[2] + 0.25f*m[3];
        out[OFF_LOSS] = 0.5f*Lc + pcf_loss + plm_loss;
    }
}

// ---------- orchestration ----------
extern "C" void kernel_launch(void* const* d_in, const int* in_sizes, int n_in,
                              void* d_out, int out_size) {
    const float* pcf = (const float*)d_in[0];
    const float* plm = (const float*)d_in[1];
    const float* emb = (const float*)d_in[2];
    float* out = (float*)d_out;

    const int SM_SC = 2 * SCBUF;   // 81920
    cudaFuncSetAttribute(k_scode_bf16, cudaFuncAttributeMaxDynamicSharedMemorySize, SM_SC);

    k_init<<<256, 256>>>(pcf, plm);
    k_rownorm<<<4096, 256>>>(emb, KS*MN, 0, 0);
    k_rownorm<<<512, 256>>>(pcf, BN, 3, 0);
    k_rownorm<<<512, 256>>>(plm, BN, 3, BN);

    // scores on original inputs (g_res pre-update)
    k_scorestc<<<dim3(64, 32, 2), 256>>>(emb);
    k_softmax<<<dim3(BN, 2), 256>>>();

    for (int s = 0; s < KS; s++) {
        k_argmin_tc<<<dim3(64, 32, 2), 256>>>(emb, s);
        k_verify<<<dim3(BN, 2), 256>>>(emb, s);
        k_update<<<1024, 256>>>(emb, s);
    }

    k_scode_bf16<<<1024, 256, SM_SC>>>();
    k_rowratio<<<BN, 256>>>();

    k_quant<<<QN/256, 256>>>(pcf, plm, out);
    k_ids<<<(2*BN*KS)/256, 256>>>(out);
    k_mse<<<256, 256>>>(pcf, plm, out);
    k_perp<<<8, 256>>>(out);
    k_final<<<1, 256>>>(out);
}

// round 17
// speedup vs baseline: 2.0988x; 2.0988x over previous
#include <cuda_runtime.h>
#include <cuda_bf16.h>
#include <cstdint>

#define BN 4096
#define DN 128
#define MN 8192
#define KS 4
#define QN (2*BN*DN)
#define HALFQ (BN*DN)
#define OFF_LOSS 1048576
#define OFF_IDS  1048577
#define OFF_PERP 1081345
#define DELTA 2e-2f

typedef unsigned long long ull;

// ---------- device scratch ----------
__device__ float g_Enorm[KS*MN];
__device__ float g_xnorm0[2*BN];
__device__ float g_xnormR[2*BN];
__device__ float g_res[QN];
__device__ float g_q[QN];
__device__ ull   g_min[2*BN];
__device__ unsigned g_minA[2*BN];
__device__ int   g_counts[KS*2*MN];
__device__ int   g_idx[2*BN*KS];
__device__ float g_ph[2ull*BN*MN];   // scores, then per-stage d_approx scratch
__device__ __align__(16) __nv_bfloat16 g_phh[2ull*BN*MN];
__device__ __align__(16) __nv_bfloat16 g_lgh[2ull*BN*MN];
__device__ float g_Sc[(size_t)BN*BN];
__device__ unsigned g_minkey;
__device__ float g_rowlog[BN];
__device__ float g_mse[256*4];

// ---------- helpers ----------
__device__ __forceinline__ unsigned sortkey(float v) {
    unsigned u = __float_as_uint(v);
    return (u & 0x80000000u) ? ~u : (u | 0x80000000u);
}
__device__ __forceinline__ float unsortkey(unsigned k) {
    return (k & 0x80000000u) ? __uint_as_float(k & 0x7FFFFFFFu)
                             : __uint_as_float(~k);
}
__device__ __forceinline__ ull packdi(float v, int idx) {
    return ((ull)sortkey(v) << 32) | (unsigned)idx;
}
__device__ __forceinline__ uint32_t smem_u32(const void* p) {
    uint32_t a;
    asm("{ .reg .u64 t; cvta.to.shared.u64 t, %1; cvt.u32.u64 %0, t; }"
        : "=r"(a) : "l"(p));
    return a;
}
__device__ __forceinline__ void mma_t(float* c, uint32_t a0, uint32_t a1,
                                      uint32_t a2, uint32_t a3,
                                      uint32_t b0, uint32_t b1) {
    asm volatile("mma.sync.aligned.m16n8k8.row.col.f32.tf32.tf32.f32 "
        "{%0,%1,%2,%3},{%4,%5,%6,%7},{%8,%9},{%0,%1,%2,%3};"
        : "+f"(c[0]), "+f"(c[1]), "+f"(c[2]), "+f"(c[3])
        : "r"(a0), "r"(a1), "r"(a2), "r"(a3), "r"(b0), "r"(b1));
}
__device__ __forceinline__ void ldsm4(uint32_t& r0, uint32_t& r1,
                                      uint32_t& r2, uint32_t& r3, uint32_t a) {
    asm volatile("ldmatrix.sync.aligned.m8n8.x4.shared.b16 {%0,%1,%2,%3}, [%4];"
        : "=r"(r0), "=r"(r1), "=r"(r2), "=r"(r3) : "r"(a));
}
__device__ __forceinline__ void mma_bf16(float* c, uint32_t a0, uint32_t a1,
                                         uint32_t a2, uint32_t a3,
                                         uint32_t b0, uint32_t b1) {
    asm volatile("mma.sync.aligned.m16n8k16.row.col.f32.bf16.bf16.f32 "
        "{%0,%1,%2,%3},{%4,%5,%6,%7},{%8,%9},{%0,%1,%2,%3};"
        : "+f"(c[0]), "+f"(c[1]), "+f"(c[2]), "+f"(c[3])
        : "r"(a0), "r"(a1), "r"(a2), "r"(a3), "r"(b0), "r"(b1));
}
#define CP_ASYNC16(s, g) asm volatile("cp.async.ca.shared.global [%0], [%1], 16;" :: "r"(s), "l"(g))
#define CP_COMMIT()      asm volatile("cp.async.commit_group;" ::: "memory")
#define CP_WAIT1()       asm volatile("cp.async.wait_group 1;" ::: "memory")
#define CP_WAIT0()       asm volatile("cp.async.wait_group 0;" ::: "memory")

// ---------- row norms: mode 0 -> g_Enorm ; mode 3 -> g_xnorm0 AND g_xnormR ----------
__global__ __launch_bounds__(256) void k_rownorm(const float* __restrict__ Xin,
                                                 int nrows, int mode, int off) {
    int w = (blockIdx.x * 256 + threadIdx.x) >> 5;
    int lane = threadIdx.x & 31;
    if (w >= nrows) return;
    float4 v = reinterpret_cast<const float4*>(Xin + (size_t)w * DN)[lane];
    float s = v.x*v.x + v.y*v.y + v.z*v.z + v.w*v.w;
    #pragma unroll
    for (int o = 16; o; o >>= 1) s += __shfl_xor_sync(0xFFFFFFFFu, s, o);
    if (lane == 0) {
        if (mode == 0) g_Enorm[off + w] = s;
        else { g_xnorm0[off + w] = s; g_xnormR[off + w] = s; }
    }
}

// ---------- init ----------
__global__ __launch_bounds__(256) void k_init(const float* __restrict__ pcf,
                                              const float* __restrict__ plm) {
    int stride = gridDim.x * 256;
    for (int i = blockIdx.x * 256 + threadIdx.x; i < QN; i += stride) {
        g_res[i] = (i < HALFQ) ? pcf[i] : plm[i - HALFQ];
        g_q[i] = 0.0f;
    }
    for (int i = blockIdx.x * 256 + threadIdx.x; i < KS*2*MN; i += stride)
        g_counts[i] = 0;
    for (int i = blockIdx.x * 256 + threadIdx.x; i < 2*BN; i += stride)
        g_minA[i] = 0xFFFFFFFFu;
    if (blockIdx.x == 0 && threadIdx.x == 0) g_minkey = 0xFFFFFFFFu;
}

// ---------- cmcm scores via tf32 tensor cores (raw-bit; bf16 downstream) ----------
__global__ __launch_bounds__(256) void k_scorestc(const float* __restrict__ emb) {
    __shared__ __align__(16) float sA[128*36];
    __shared__ __align__(16) float sB[128*36];
    const int tid = threadIdx.x;
    const int lane = tid & 31, wid = tid >> 5;
    const int wy = wid & 3, wx = wid >> 2;
    const int stream = blockIdx.z;
    const int b0 = blockIdx.y * 128;
    const int m0 = blockIdx.x * 128;
    const float* resp = g_res + (size_t)stream * HALFQ;   // original inputs (pre-update)
    const float* Ep = emb + (size_t)(KS-1) * MN * DN;
    const float* En = g_Enorm + (KS-1)*MN;
    const float* xnorm = g_xnorm0 + stream * BN;

    float acc[2][8][4];
    #pragma unroll
    for (int mt = 0; mt < 2; mt++)
        #pragma unroll
        for (int n8 = 0; n8 < 8; n8++)
            #pragma unroll
            for (int c = 0; c < 4; c++) acc[mt][n8][c] = 0.0f;

    const uint32_t sAu = smem_u32(sA), sBu = smem_u32(sB);
    const int l4 = lane >> 2, l3 = lane & 3;

    for (int chk = 0; chk < 4; chk++) {
        int kb = chk * 32;
        #pragma unroll
        for (int i = 0; i < 4; i++) {
            int v = tid + i*256;
            int row = v >> 3, c4 = (v & 7) * 4;
            CP_ASYNC16(sAu + (uint32_t)(row*36 + c4)*4,
                       resp + (size_t)(b0 + row)*DN + kb + c4);
        }
        #pragma unroll
        for (int i = 0; i < 4; i++) {
            int v = tid + i*256;
            int row = v >> 3, c4 = (v & 7) * 4;
            CP_ASYNC16(sBu + (uint32_t)(row*36 + c4)*4,
                       Ep + (size_t)(m0 + row)*DN + kb + c4);
        }
        CP_COMMIT(); CP_WAIT0();
        __syncthreads();
        #pragma unroll
        for (int k8 = 0; k8 < 4; k8++) {
            const int kk = k8*8 + l3;
            uint32_t aH[2][4];
            #pragma unroll
            for (int mt = 0; mt < 2; mt++) {
                int r = wy*32 + mt*16 + l4;
                aH[mt][0] = __float_as_uint(sA[r*36 + kk]);
                aH[mt][1] = __float_as_uint(sA[(r+8)*36 + kk]);
                aH[mt][2] = __float_as_uint(sA[r*36 + kk + 4]);
                aH[mt][3] = __float_as_uint(sA[(r+8)*36 + kk + 4]);
            }
            #pragma unroll
            for (int n8 = 0; n8 < 8; n8++) {
                int n = wx*64 + n8*8 + l4;
                uint32_t bH0 = __float_as_uint(sB[n*36 + kk]);
                uint32_t bH1 = __float_as_uint(sB[n*36 + kk + 4]);
                #pragma unroll
                for (int mt = 0; mt < 2; mt++)
                    mma_t(acc[mt][n8], aH[mt][0], aH[mt][1], aH[mt][2], aH[mt][3], bH0, bH1);
            }
        }
        __syncthreads();
    }

    float xv[2][2];
    #pragma unroll
    for (int mt = 0; mt < 2; mt++) {
        xv[mt][0] = xnorm[b0 + wy*32 + mt*16 + l4];
        xv[mt][1] = xnorm[b0 + wy*32 + mt*16 + l4 + 8];
    }
    size_t sbase = (size_t)stream*BN*MN;
    #pragma unroll
    for (int mt = 0; mt < 2; mt++) {
        int r = b0 + wy*32 + mt*16 + l4;
        #pragma unroll
        for (int n8 = 0; n8 < 8; n8++) {
            int c0 = m0 + wx*64 + n8*8 + l3*2;
            float e0 = En[c0], e1 = En[c0+1];
            float* a = acc[mt][n8];
            float2 o0, o1;
            o0.x = -sqrtf(fmaxf((e0 + xv[mt][0]) - 2.0f*a[0], 0.0f));
            o0.y = -sqrtf(fmaxf((e1 + xv[mt][0]) - 2.0f*a[1], 0.0f));
            o1.x = -sqrtf(fmaxf((e0 + xv[mt][1]) - 2.0f*a[2], 0.0f));
            o1.y = -sqrtf(fmaxf((e1 + xv[mt][1]) - 2.0f*a[3], 0.0f));
            *(float2*)&g_ph[sbase + (size_t)r*MN + c0]     = o0;
            *(float2*)&g_ph[sbase + (size_t)(r+8)*MN + c0] = o1;
        }
    }
}

// ---------- argmin filter: single tf32 GEMM (raw-bit), stores d_approx + row min ----------
__global__ __launch_bounds__(256) void k_argmin_tc(const float* __restrict__ emb,
                                                   int stage) {
    __shared__ __align__(16) float sA[128*36];
    __shared__ __align__(16) float sB[128*36];
    const int tid = threadIdx.x;
    const int lane = tid & 31, wid = tid >> 5;
    const int wy = wid & 3, wx = wid >> 2;
    const int stream = blockIdx.z;
    const int b0 = blockIdx.y * 128;
    const int m0 = blockIdx.x * 128;
    const float* resp = g_res + (size_t)stream * HALFQ;
    const float* Ep = emb + (size_t)stage * MN * DN;
    const float* En = g_Enorm + stage * MN;
    const float* xnorm = g_xnormR + stream * BN;

    float acc[2][8][4];
    #pragma unroll
    for (int mt = 0; mt < 2; mt++)
        #pragma unroll
        for (int n8 = 0; n8 < 8; n8++)
            #pragma unroll
            for (int c = 0; c < 4; c++) acc[mt][n8][c] = 0.0f;

    const uint32_t sAu = smem_u32(sA), sBu = smem_u32(sB);
    const int l4 = lane >> 2, l3 = lane & 3;

    for (int chk = 0; chk < 4; chk++) {
        int kb = chk * 32;
        #pragma unroll
        for (int i = 0; i < 4; i++) {
            int v = tid + i*256;
            int row = v >> 3, c4 = (v & 7) * 4;
            CP_ASYNC16(sAu + (uint32_t)(row*36 + c4)*4,
                       resp + (size_t)(b0 + row)*DN + kb + c4);
        }
        #pragma unroll
        for (int i = 0; i < 4; i++) {
            int v = tid + i*256;
            int row = v >> 3, c4 = (v & 7) * 4;
            CP_ASYNC16(sBu + (uint32_t)(row*36 + c4)*4,
                       Ep + (size_t)(m0 + row)*DN + kb + c4);
        }
        CP_COMMIT(); CP_WAIT0();
        __syncthreads();
        #pragma unroll
        for (int k8 = 0; k8 < 4; k8++) {
            const int kk = k8*8 + l3;
            uint32_t aH[2][4];
            #pragma unroll
            for (int mt = 0; mt < 2; mt++) {
                int r = wy*32 + mt*16 + l4;
                aH[mt][0] = __float_as_uint(sA[r*36 + kk]);
                aH[mt][1] = __float_as_uint(sA[(r+8)*36 + kk]);
                aH[mt][2] = __float_as_uint(sA[r*36 + kk + 4]);
                aH[mt][3] = __float_as_uint(sA[(r+8)*36 + kk + 4]);
            }
            #pragma unroll
            for (int n8 = 0; n8 < 8; n8++) {
                int n = wx*64 + n8*8 + l4;
                uint32_t bH0 = __float_as_uint(sB[n*36 + kk]);
                uint32_t bH1 = __float_as_uint(sB[n*36 + kk + 4]);
                #pragma unroll
                for (int mt = 0; mt < 2; mt++)
                    mma_t(acc[mt][n8], aH[mt][0], aH[mt][1], aH[mt][2], aH[mt][3], bH0, bH1);
            }
        }
        __syncthreads();
    }

    float xv[2][2];
    #pragma unroll
    for (int mt = 0; mt < 2; mt++) {
        xv[mt][0] = xnorm[b0 + wy*32 + mt*16 + l4];
        xv[mt][1] = xnorm[b0 + wy*32 + mt*16 + l4 + 8];
    }
    size_t sbase = (size_t)stream*BN*MN;
    unsigned best[2][2] = {{~0u, ~0u}, {~0u, ~0u}};
    #pragma unroll
    for (int mt = 0; mt < 2; mt++) {
        int r = b0 + wy*32 + mt*16 + l4;
        #pragma unroll
        for (int n8 = 0; n8 < 8; n8++) {
            int c0 = m0 + wx*64 + n8*8 + l3*2;
            float e0 = En[c0], e1 = En[c0+1];
            float* a = acc[mt][n8];
            float d00 = (e0 + xv[mt][0]) - 2.0f*a[0];
            float d01 = (e1 + xv[mt][0]) - 2.0f*a[1];
            float d10 = (e0 + xv[mt][1]) - 2.0f*a[2];
            float d11 = (e1 + xv[mt][1]) - 2.0f*a[3];
            *(float2*)&g_ph[sbase + (size_t)r*MN + c0]     = make_float2(d00, d01);
            *(float2*)&g_ph[sbase + (size_t)(r+8)*MN + c0] = make_float2(d10, d11);
            unsigned m0v = min(sortkey(d00), sortkey(d01));
            unsigned m1v = min(sortkey(d10), sortkey(d11));
            if (m0v < best[mt][0]) best[mt][0] = m0v;
            if (m1v < best[mt][1]) best[mt][1] = m1v;
        }
    }
    __syncthreads();
    unsigned* sred = (unsigned*)sA;
    #pragma unroll
    for (int mt = 0; mt < 2; mt++)
        #pragma unroll
        for (int h = 0; h < 2; h++)
            sred[(wy*32 + mt*16 + h*8 + l4)*8 + wx*4 + l3] = best[mt][h];
    __syncthreads();
    if (tid < 128) {
        unsigned kk = sred[tid*8];
        #pragma unroll
        for (int t = 1; t < 8; t++) { unsigned c = sred[tid*8 + t]; if (c < kk) kk = c; }
        atomicMin(&g_minA[(size_t)stream*BN + b0 + tid], kk);
    }
}

// ---------- argmin verify: per-element threshold, exact serial rescore (R13-proven) ----------
__global__ __launch_bounds__(256) void k_verify(const float* __restrict__ emb, int stage) {
    __shared__ __align__(16) float resS[DN];
    __shared__ ull red[256];
    const int row = blockIdx.x, stream = blockIdx.y, tid = threadIdx.x;
    const float* resp = g_res + (size_t)stream*HALFQ + (size_t)row*DN;
    if (tid < 32) reinterpret_cast<float4*>(resS)[tid] = reinterpret_cast<const float4*>(resp)[tid];
    float xn = g_xnormR[stream*BN + row];
    float thr = unsortkey(g_minA[stream*BN + row]) + DELTA;
    __syncthreads();
    const float* dap = g_ph + (size_t)stream*BN*MN + (size_t)row*MN;
    const float* Ep = emb + (size_t)stage*MN*DN;
    const float* En = g_Enorm + stage*MN;
    ull best = ~0ull;
    #pragma unroll 4
    for (int m = tid; m < MN; m += 256) {
        float da = dap[m];
        if (da <= thr) {
            const float* Er = Ep + (size_t)m*DN;
            float acc = 0.0f;
            #pragma unroll 16
            for (int d = 0; d < DN; d++) acc = fmaf(resS[d], Er[d], acc);
            float val = (En[m] + xn) - 2.0f*acc;
            ull p = packdi(val, m);
            if (p < best) best = p;
        }
    }
    red[tid] = best; __syncthreads();
    for (int o = 128; o > 0; o >>= 1) {
        if (tid < o) { ull c = red[tid + o]; if (c < red[tid]) red[tid] = c; }
        __syncthreads();
    }
    if (tid == 0) g_min[stream*BN + row] = red[0];
}

// ---------- gather + residual/q update + histogram + norm + minA reset ----------
__global__ __launch_bounds__(256) void k_update(const float* __restrict__ emb, int stage) {
    int w = (blockIdx.x * 256 + threadIdx.x) >> 5;
    int lane = threadIdx.x & 31;
    if (w >= 2*BN) return;
    int stream = w >> 12; int b = w & (BN - 1);
    int idx = (int)(g_min[w] & 0xFFFFFFFFull);
    float4 e = reinterpret_cast<const float4*>(emb + ((size_t)stage*MN + idx)*DN)[lane];
    float4* qp = reinterpret_cast<float4*>(g_q + (size_t)w*DN);
    float4* rp = reinterpret_cast<float4*>(g_res + (size_t)w*DN);
    float4 q = qp[lane]; q.x += e.x; q.y += e.y; q.z += e.z; q.w += e.w; qp[lane] = q;
    float4 r = rp[lane]; r.x -= e.x; r.y -= e.y; r.z -= e.z; r.w -= e.w; rp[lane] = r;
    float s = r.x*r.x + r.y*r.y + r.z*r.z + r.w*r.w;
    #pragma unroll
    for (int o = 16; o; o >>= 1) s += __shfl_xor_sync(0xFFFFFFFFu, s, o);
    if (lane == 0) {
        g_xnormR[w] = s;
        g_idx[stream*BN*KS + b*KS + stage] = idx;
        atomicAdd(&g_counts[(stage*2 + stream)*MN + idx], 1);
        g_minA[w] = 0xFFFFFFFFu;
    }
}

// ---------- row softmax + log -> bf16 outputs ----------
__global__ __launch_bounds__(256) void k_softmax() {
    __shared__ __align__(16) float srow[MN];
    __shared__ float red[256];
    int b = blockIdx.x, s = blockIdx.y, tid = threadIdx.x;
    size_t base = (size_t)s*BN*MN + (size_t)b*MN;
    const float4* src = reinterpret_cast<const float4*>(g_ph + base);
    float mx = -3.4e38f;
    #pragma unroll
    for (int k = 0; k < 8; k++) {
        float4 v = src[tid + 256*k];
        reinterpret_cast<float4*>(srow)[tid + 256*k] = v;
        mx = fmaxf(mx, fmaxf(fmaxf(v.x, v.y), fmaxf(v.z, v.w)));
    }
    red[tid] = mx; __syncthreads();
    for (int o = 128; o > 0; o >>= 1) {
        if (tid < o) red[tid] = fmaxf(red[tid], red[tid + o]);
        __syncthreads();
    }
    mx = red[0]; __syncthreads();
    float sum = 0.0f;
    #pragma unroll
    for (int k = 0; k < 8; k++) {
        float4 v = reinterpret_cast<float4*>(srow)[tid + 256*k];
        v.x = expf(v.x - mx); v.y = expf(v.y - mx);
        v.z = expf(v.z - mx); v.w = expf(v.w - mx);
        reinterpret_cast<float4*>(srow)[tid + 256*k] = v;
        sum += v.x + v.y + v.z + v.w;
    }
    red[tid] = sum; __syncthreads();
    for (int o = 128; o > 0; o >>= 1) {
        if (tid < o) red[tid] = red[tid] + red[tid + o];
        __syncthreads();
    }
    sum = red[0];
    __nv_bfloat162* dph = reinterpret_cast<__nv_bfloat162*>(g_phh + base);
    __nv_bfloat162* dlg = reinterpret_cast<__nv_bfloat162*>(g_lgh + base);
    #pragma unroll
    for (int k = 0; k < 8; k++) {
        float4 v = reinterpret_cast<float4*>(srow)[tid + 256*k];
        v.x /= sum; v.y /= sum; v.z /= sum; v.w /= sum;
        int p = (tid + 256*k) * 2;
        dph[p]   = __floats2bfloat162_rn(v.x, v.y);
        dph[p+1] = __floats2bfloat162_rn(v.z, v.w);
        dlg[p]   = __floats2bfloat162_rn(logf(v.x + 1e-10f), logf(v.y + 1e-10f));
        dlg[p+1] = __floats2bfloat162_rn(logf(v.z + 1e-10f), logf(v.w + 1e-10f));
    }
}

// ---------- Scode via bf16 mma.m16n8k16, ldmatrix, cp.async double buffer ----------
#define SCT 10240
#define SCBUF (4*SCT)
__global__ __launch_bounds__(256) void k_scode_bf16() {
    extern __shared__ __align__(16) char smc[];
    const uint32_t sb = smem_u32(smc);
    const int tid = threadIdx.x;
    const int lane = tid & 31, wid = tid >> 5;
    const int wy = wid & 3, wx = wid >> 2;
    const int i0 = (blockIdx.x & 31) * 128;
    const int j0 = (blockIdx.x >> 5) * 128;
    const __nv_bfloat16* A1g = g_phh + (size_t)i0 * MN;
    const __nv_bfloat16* A2g = g_phh + (size_t)BN*MN + (size_t)i0 * MN;
    const __nv_bfloat16* B1g = g_lgh + (size_t)BN*MN + (size_t)j0 * MN;
    const __nv_bfloat16* B2g = g_lgh + (size_t)j0 * MN;

    float acc[2][8][4];
    #pragma unroll
    for (int mi = 0; mi < 2; mi++)
        #pragma unroll
        for (int n8 = 0; n8 < 8; n8++)
            #pragma unroll
            for (int c = 0; c < 4; c++) acc[mi][n8][c] = 0.0f;

    const int m = lane >> 3, l7 = lane & 7;
    const uint32_t aoff = (uint32_t)(((m & 1)*8 + l7) * 80 + (m >> 1) * 16);
    const uint32_t boff = (uint32_t)(((m >> 1)*8 + l7) * 80 + (m & 1) * 16);

    auto stage = [&](int kc, int bsel) {
        int kb = kc * 32;
        uint32_t d0 = sb + bsel * SCBUF;
        #pragma unroll
        for (int it = 0; it < 8; it++) {
            int t = tid + it*256;
            int mat = t >> 9, r = (t >> 2) & 127, c = t & 3;
            const __nv_bfloat16* srcp = (mat == 0) ? A1g : (mat == 1) ? A2g
                                      : (mat == 2) ? B1g : B2g;
            const void* g = srcp + (size_t)r*MN + kb + c*8;
            uint32_t sdst = d0 + mat*SCT + r*80 + c*16;
            CP_ASYNC16(sdst, g);
        }
        CP_COMMIT();
    };

    stage(0, 0);
    for (int kc = 0; kc < 256; kc++) {
        if (kc + 1 < 256) { stage(kc + 1, (kc + 1) & 1); CP_WAIT1(); }
        else CP_WAIT0();
        __syncthreads();
        uint32_t base = sb + (kc & 1) * SCBUF;
        #pragma unroll
        for (int s = 0; s < 2; s++) {
            #pragma unroll
            for (int g = 0; g < 2; g++) {
                uint32_t ab = base + g*SCT + (wy*32)*80 + s*32 + aoff;
                uint32_t a0[2], a1[2], a2[2], a3[2];
                #pragma unroll
                for (int mi = 0; mi < 2; mi++)
                    ldsm4(a0[mi], a1[mi], a2[mi], a3[mi], ab + mi*16*80);
                uint32_t bbase = base + (2 + g)*SCT + (wx*64)*80 + s*32 + boff;
                #pragma unroll
                for (int gg = 0; gg < 4; gg++) {
                    uint32_t b0, b1, b2, b3;
                    ldsm4(b0, b1, b2, b3, bbase + gg*16*80);
                    #pragma unroll
                    for (int mi = 0; mi < 2; mi++) {
                        mma_bf16(acc[mi][gg*2+0], a0[mi], a1[mi], a2[mi], a3[mi], b0, b1);
                        mma_bf16(acc[mi][gg*2+1], a0[mi], a1[mi], a2[mi], a3[mi], b2, b3);
                    }
                }
            }
        }
        __syncthreads();
    }
    float lmin = 3.4e38f;
    #pragma unroll
    for (int mi = 0; mi < 2; mi++) {
        int row = i0 + wy*32 + mi*16 + (lane >> 2);
        #pragma unroll
        for (int n8 = 0; n8 < 8; n8++) {
            int col = j0 + wx*64 + n8*8 + (lane & 3)*2;
            float* c = acc[mi][n8];
            *(float2*)&g_Sc[(size_t)row*BN + col]     = make_float2(c[0], c[1]);
            *(float2*)&g_Sc[(size_t)(row+8)*BN + col] = make_float2(c[2], c[3]);
            lmin = fminf(lmin, fminf(fminf(c[0], c[1]), fminf(c[2], c[3])));
        }
    }
    float* red = (float*)smc;
    red[tid] = lmin; __syncthreads();
    for (int o = 128; o > 0; o >>= 1) {
        if (tid < o) red[tid] = fminf(red[tid], red[tid + o]);
        __syncthreads();
    }
    if (tid == 0) atomicMin(&g_minkey, sortkey(red[0]));
}

// ---------- per-row: log(diag(E)/(rowsum(E)+eps)) ----------
__global__ __launch_bounds__(256) void k_rowratio() {
    __shared__ float red[256];
    int i = blockIdx.x, tid = threadIdx.x;
    float Mx = -unsortkey(g_minkey);
    const float* row = g_Sc + (size_t)i * BN;
    float sum = 0.0f;
    #pragma unroll
    for (int k = 0; k < 16; k++) sum += expf(row[tid + 256*k] + Mx);
    red[tid] = sum; __syncthreads();
    for (int o = 128; o > 0; o >>= 1) {
        if (tid < o) red[tid] = red[tid] + red[tid + o];
        __syncthreads();
    }
    if (tid == 0) {
        float ratio = expf(row[i] + Mx) / (red[0] + 1e-5f);
        g_rowlog[i] = logf(ratio);
    }
}

// ---------- quantized = fl(x + fl(q - x)) ----------
__global__ __launch_bounds__(256) void k_quant(const float* __restrict__ pcf,
                                               const float* __restrict__ plm,
                                               float* __restrict__ out) {
    int e = blockIdx.x * 256 + threadIdx.x;
    if (e >= QN) return;
    float x = (e < HALFQ) ? pcf[e] : plm[e - HALFQ];
    float t = g_q[e] - x;
    out[e] = x + t;
}

__global__ __launch_bounds__(256) void k_ids(float* __restrict__ out) {
    int e = blockIdx.x * 256 + threadIdx.x;
    if (e < 2*BN*KS) out[OFF_IDS + e] = (float)g_idx[e];
}

__global__ __launch_bounds__(256) void k_mse(const float* __restrict__ pcf,
                                             const float* __restrict__ plm,
                                             const float* __restrict__ out) {
    __shared__ float red[256];
    int tid = threadIdx.x, bid = blockIdx.x;
    float s[4] = {0.f, 0.f, 0.f, 0.f};
    #pragma unroll
    for (int k = 0; k < 8; k++) {
        int e = bid*2048 + k*256 + tid;
        float qp = out[e], qm = out[HALFQ + e];
        float xp = pcf[e], xm = plm[e];
        float d;
        d = xp - qp; s[0] += d*d;
        d = xp - qm; s[1] += d*d;
        d = xm - qm; s[2] += d*d;
        d = xm - qp; s[3] += d*d;
    }
    #pragma unroll
    for (int c = 0; c < 4; c++) {
        red[tid] = s[c]; __syncthreads();
        for (int o = 128; o > 0; o >>= 1) {
            if (tid < o) red[tid] = red[tid] + red[tid + o];
            __syncthreads();
        }
        if (tid == 0) g_mse[bid*4 + c] = red[0];
        __syncthreads();
    }
}

__global__ __launch_bounds__(256) void k_perp(float* __restrict__ out) {
    __shared__ float red[256];
    int b = blockIdx.x, tid = threadIdx.x;
    int k = b >> 1, s = b & 1;
    const int* cnt = g_counts + (k*2 + s)*MN;
    float sum = 0.0f;
    #pragma unroll
    for (int t = 0; t < 32; t++) {
        float avg = (float)cnt[tid + 256*t] / (float)BN;
        sum += avg * logf(avg + 1e-10f);
    }
    red[tid] = sum; __syncthreads();
    for (int o = 128; o > 0; o >>= 1) {
        if (tid < o) red[tid] = red[tid] + red[tid + o];
        __syncthreads();
    }
    if (tid == 0) out[OFF_PERP + k*2 + s] = expf(-red[0]);
}

__global__ __launch_bounds__(256) void k_final(float* __restrict__ out) {
    __shared__ float red[256];
    int tid = threadIdx.x;
    float s = 0.0f;
    #pragma unroll
    for (int k = 0; k < 16; k++) s += g_rowlog[tid + 256*k];
    red[tid] = s; __syncthreads();
    for (int o = 128; o > 0; o >>= 1) {
        if (tid < o) red[tid] = red[tid] + red[tid + o];
        __syncthreads();
    }
    float Lc = -(red[0] / (float)BN);
    __syncthreads();
    float m[4];
    for (int c = 0; c < 4; c++) {
        red[tid] = g_mse[tid*4 + c]; __syncthreads();
        for (int o = 128; o > 0; o >>= 1) {
            if (tid < o) red[tid] = red[tid] + red[tid + o];
            __syncthreads();
        }
        m[c] = red[0] / (float)HALFQ;
        __syncthreads();
    }
    if (tid == 0) {
        float pcf_loss = 0.5f*m[0] + 0.25f*m[1];
        float plm_loss = 0.5f*m[2] + 0.25f*m[3];
        out[OFF_LOSS] = 0.5f*Lc + pcf_loss + plm_loss;
    }
}

// ---------- orchestration ----------
extern "C" void kernel_launch(void* const* d_in, const int* in_sizes, int n_in,
                              void* d_out, int out_size) {
    const float* pcf = (const float*)d_in[0];
    const float* plm = (const float*)d_in[1];
    const float* emb = (const float*)d_in[2];
    float* out = (float*)d_out;

    const int SM_SC = 2 * SCBUF;   // 81920
    cudaFuncSetAttribute(k_scode_bf16, cudaFuncAttributeMaxDynamicSharedMemorySize, SM_SC);

    k_init<<<256, 256>>>(pcf, plm);
    k_rownorm<<<4096, 256>>>(emb, KS*MN, 0, 0);
    k_rownorm<<<512, 256>>>(pcf, BN, 3, 0);
    k_rownorm<<<512, 256>>>(plm, BN, 3, BN);

    // scores on original inputs (g_res pre-update), then softmax frees g_ph
    k_scorestc<<<dim3(64, 32, 2), 256>>>(emb);
    k_softmax<<<dim3(BN, 2), 256>>>();

    for (int s = 0; s < KS; s++) {
        k_argmin_tc<<<dim3(64, 32, 2), 256>>>(emb, s);
        k_verify<<<dim3(BN, 2), 256>>>(emb, s);
        k_update<<<1024, 256>>>(emb, s);
    }

    k_scode_bf16<<<1024, 256, SM_SC>>>();
    k_rowratio<<<BN, 256>>>();

    k_quant<<<QN/256, 256>>>(pcf, plm, out);
    k_ids<<<(2*BN*KS)/256, 256>>>(out);
    k_mse<<<256, 256>>>(pcf, plm, out);
    k_perp<<<8, 256>>>(out);
    k_final<<<1, 256>>>(out);
}